// round 1
// baseline (speedup 1.0000x reference)
#include <cuda_runtime.h>
#include <cstdint>

// Problem constants
namespace {
constexpr int L3c  = 17 * 17 * 17;     // 4913 LUT entries
constexpr int HWc  = 1080 * 1920;      // 2,073,600 pixels per plane
constexpr int Gc   = HWc / 4;          // 518,400 float4 groups per plane
constexpr int TOTALG = 2 * Gc;         // both batches
constexpr int SMEM_BYTES = L3c * 16;   // 78,608 B (float4 per entry)
}

// Folded LUT: e[idx] = (clip(rint(lut*127),-127,127) @ ccm.T), padded to float4
__device__ float4 g_lutc[L3c];

__global__ void prep_kernel(const float* __restrict__ lut,
                            const float* __restrict__ ccm) {
    int i = blockIdx.x * blockDim.x + threadIdx.x;
    if (i >= L3c) return;
    float w0 = fminf(fmaxf(rintf(lut[3 * i + 0] * 127.0f), -127.0f), 127.0f);
    float w1 = fminf(fmaxf(rintf(lut[3 * i + 1] * 127.0f), -127.0f), 127.0f);
    float w2 = fminf(fmaxf(rintf(lut[3 * i + 2] * 127.0f), -127.0f), 127.0f);
    // out[c'] = sum_c w[c] * ccm[c'][c]   (ccm row-major [3,3])
    float e0 = w0 * ccm[0] + w1 * ccm[1] + w2 * ccm[2];
    float e1 = w0 * ccm[3] + w1 * ccm[4] + w2 * ccm[5];
    float e2 = w0 * ccm[6] + w1 * ccm[7] + w2 * ccm[8];
    g_lutc[i] = make_float4(e0, e1, e2, 0.0f);
}

__device__ __forceinline__ float lerpf(float a, float b, float t) {
    return fmaf(b - a, t, a);
}

// One pixel: trilinear gather from smem folded LUT + clamp.
__device__ __forceinline__ void px_one(const float4* __restrict__ slut,
                                       float r, float g, float b,
                                       float& o0, float& o1, float& o2) {
    // r/16 is exact (power-of-2 scale); fr == mod(r,16)/16 bit-exactly
    float rf = r * 0.0625f, gf = g * 0.0625f, bf = b * 0.0625f;
    float rfl = floorf(rf), gfl = floorf(gf), bfl = floorf(bf);
    float fr = rf - rfl, fg = gf - gfl, fb = bf - bfl;
    // base index = r1*289 + g1*17 + b1, exact integer FMA in fp32 (max 4605)
    int base = (int)fmaf(rfl, 289.0f, fmaf(gfl, 17.0f, bfl));
    const float4* c = slut + base;
    // inputs are in [0,255) so r1,g1,b1 <= 15 -> all offsets in range, no clip
    float4 p000 = c[0],   p001 = c[1];
    float4 p010 = c[17],  p011 = c[18];
    float4 p100 = c[289], p101 = c[290];
    float4 p110 = c[306], p111 = c[307];

    float c00x = lerpf(p000.x, p100.x, fr);
    float c00y = lerpf(p000.y, p100.y, fr);
    float c00z = lerpf(p000.z, p100.z, fr);
    float c01x = lerpf(p001.x, p101.x, fr);
    float c01y = lerpf(p001.y, p101.y, fr);
    float c01z = lerpf(p001.z, p101.z, fr);
    float c10x = lerpf(p010.x, p110.x, fr);
    float c10y = lerpf(p010.y, p110.y, fr);
    float c10z = lerpf(p010.z, p110.z, fr);
    float c11x = lerpf(p011.x, p111.x, fr);
    float c11y = lerpf(p011.y, p111.y, fr);
    float c11z = lerpf(p011.z, p111.z, fr);

    float c0x = lerpf(c00x, c10x, fg);
    float c0y = lerpf(c00y, c10y, fg);
    float c0z = lerpf(c00z, c10z, fg);
    float c1x = lerpf(c01x, c11x, fg);
    float c1y = lerpf(c01y, c11y, fg);
    float c1z = lerpf(c01z, c11z, fg);

    float ox = lerpf(c0x, c1x, fb);
    float oy = lerpf(c0y, c1y, fb);
    float oz = lerpf(c0z, c1z, fb);

    o0 = fminf(fmaxf(ox, 1e-8f), 1.0f);
    o1 = fminf(fmaxf(oy, 1e-8f), 1.0f);
    o2 = fminf(fmaxf(oz, 1e-8f), 1.0f);
}

__global__ void __launch_bounds__(256, 2)
lut_kernel(const float* __restrict__ img, float* __restrict__ out) {
    extern __shared__ float4 slut[];
    for (int i = threadIdx.x; i < L3c; i += 256) slut[i] = g_lutc[i];
    __syncthreads();

    const float4* in4 = (const float4*)img;
    float4* out4 = (float4*)out;
    const int stride = gridDim.x * blockDim.x;

    for (int idx = blockIdx.x * blockDim.x + threadIdx.x; idx < TOTALG;
         idx += stride) {
        // batch = 2, so a compare replaces the division
        int bb = (idx >= Gc) ? 1 : 0;
        int p  = idx - bb * Gc;
        const float4* bi = in4 + (size_t)bb * 3 * Gc;
        float4 rr = bi[p];
        float4 gg = bi[p + Gc];
        float4 bz = bi[p + 2 * Gc];

        float4 q0, q1, q2;
        px_one(slut, rr.x, gg.x, bz.x, q0.x, q1.x, q2.x);
        px_one(slut, rr.y, gg.y, bz.y, q0.y, q1.y, q2.y);
        px_one(slut, rr.z, gg.z, bz.z, q0.z, q1.z, q2.z);
        px_one(slut, rr.w, gg.w, bz.w, q0.w, q1.w, q2.w);

        float4* bo = out4 + (size_t)bb * 3 * Gc;
        bo[p]          = q0;
        bo[p + Gc]     = q1;
        bo[p + 2 * Gc] = q2;
    }
}

extern "C" void kernel_launch(void* const* d_in, const int* in_sizes, int n_in,
                              void* d_out, int out_size) {
    const float* img = (const float*)d_in[0];
    const float* lut = (const float*)d_in[1];
    const float* ccm = (const float*)d_in[2];
    float* out = (float*)d_out;

    // Opt-in to >48KB dynamic smem (idempotent, not a stream op; capture-safe)
    cudaFuncSetAttribute(lut_kernel,
                         cudaFuncAttributeMaxDynamicSharedMemorySize,
                         SMEM_BYTES);

    prep_kernel<<<(L3c + 255) / 256, 256>>>(lut, ccm);
    lut_kernel<<<296, 256, SMEM_BYTES>>>(img, out);
}

// round 2
// speedup vs baseline: 1.0494x; 1.0494x over previous
#include <cuda_runtime.h>
#include <cuda_fp16.h>
#include <cstdint>

namespace {
constexpr int L3c  = 17 * 17 * 17;     // 4913 LUT entries
constexpr int HWc  = 1080 * 1920;      // pixels per plane
constexpr int Gc   = HWc / 4;          // float4 groups per plane
constexpr int TOTALG = 2 * Gc;         // both batches
constexpr int SMEM_BYTES = L3c * 16;   // 78,608 B (one uint4 per entry)
}

// Pair-packed folded LUT: entry i holds fp16 {e0,e1,e2} of i and of i+1.
// e[i] = clip(rint(lut[i]*127),-127,127) @ ccm.T  (CCM folded into LUT).
__device__ uint4 g_lutp[L3c];

__device__ __forceinline__ void fold_entry(const float* __restrict__ lut,
                                           const float* __restrict__ ccm,
                                           int i, float& e0, float& e1, float& e2) {
    float w0 = fminf(fmaxf(rintf(lut[3 * i + 0] * 127.0f), -127.0f), 127.0f);
    float w1 = fminf(fmaxf(rintf(lut[3 * i + 1] * 127.0f), -127.0f), 127.0f);
    float w2 = fminf(fmaxf(rintf(lut[3 * i + 2] * 127.0f), -127.0f), 127.0f);
    e0 = w0 * ccm[0] + w1 * ccm[1] + w2 * ccm[2];
    e1 = w0 * ccm[3] + w1 * ccm[4] + w2 * ccm[5];
    e2 = w0 * ccm[6] + w1 * ccm[7] + w2 * ccm[8];
}

__global__ void prep_kernel(const float* __restrict__ lut,
                            const float* __restrict__ ccm) {
    int i = blockIdx.x * blockDim.x + threadIdx.x;
    if (i >= L3c) return;
    float a0, a1, a2, b0, b1, b2;
    fold_entry(lut, ccm, i, a0, a1, a2);
    int j = (i + 1 < L3c) ? i + 1 : i;   // guard; last entry's pair never read
    fold_entry(lut, ccm, j, b0, b1, b2);
    __half2 h01 = __floats2half2_rn(a0, a1);
    __half2 h23 = __floats2half2_rn(a2, b0);
    __half2 h45 = __floats2half2_rn(b1, b2);
    uint4 v;
    v.x = *reinterpret_cast<uint32_t*>(&h01);
    v.y = *reinterpret_cast<uint32_t*>(&h23);
    v.z = *reinterpret_cast<uint32_t*>(&h45);
    v.w = 0u;
    g_lutp[i] = v;
}

__device__ __forceinline__ float lerpf(float a, float b, float t) {
    return fmaf(b - a, t, a);
}

// Decode one pair entry and lerp along b in one go.
__device__ __forceinline__ void pair_blerp(uint4 P, float fb,
                                           float& q0, float& q1, float& q2) {
    float2 a = __half22float2(*reinterpret_cast<__half2*>(&P.x)); // e0(b1), e1(b1)
    float2 b = __half22float2(*reinterpret_cast<__half2*>(&P.y)); // e2(b1), e0(b2)
    float2 c = __half22float2(*reinterpret_cast<__half2*>(&P.z)); // e1(b2), e2(b2)
    q0 = lerpf(a.x, b.y, fb);
    q1 = lerpf(a.y, c.x, fb);
    q2 = lerpf(b.x, c.y, fb);
}

__device__ __forceinline__ void px_one(const uint4* __restrict__ slut,
                                       float r, float g, float b,
                                       float& o0, float& o1, float& o2) {
    float rf = r * 0.0625f, gf = g * 0.0625f, bf = b * 0.0625f;
    float rfl = floorf(rf), gfl = floorf(gf), bfl = floorf(bf);
    float fr = rf - rfl, fg = gf - gfl, fb = bf - bfl;
    // base = r1*289 + g1*17 + b1 (exact in fp32; max 4605). img<256 -> no clip.
    int base = (int)fmaf(rfl, 289.0f, fmaf(gfl, 17.0f, bfl));
    const uint4* c = slut + base;
    uint4 P00 = c[0];     // (r1,g1) b-pair
    uint4 P01 = c[17];    // (r1,g2)
    uint4 P10 = c[289];   // (r2,g1)
    uint4 P11 = c[306];   // (r2,g2)

    float a0, a1, a2, b0, b1, b2, d0, d1, d2, e0, e1, e2;
    pair_blerp(P00, fb, a0, a1, a2);
    pair_blerp(P01, fb, b0, b1, b2);
    pair_blerp(P10, fb, d0, d1, d2);
    pair_blerp(P11, fb, e0, e1, e2);

    float c0x = lerpf(a0, b0, fg);
    float c0y = lerpf(a1, b1, fg);
    float c0z = lerpf(a2, b2, fg);
    float c1x = lerpf(d0, e0, fg);
    float c1y = lerpf(d1, e1, fg);
    float c1z = lerpf(d2, e2, fg);

    o0 = fminf(fmaxf(lerpf(c0x, c1x, fr), 1e-8f), 1.0f);
    o1 = fminf(fmaxf(lerpf(c0y, c1y, fr), 1e-8f), 1.0f);
    o2 = fminf(fmaxf(lerpf(c0z, c1z, fr), 1e-8f), 1.0f);
}

__global__ void __launch_bounds__(512, 2)
lut_kernel(const float* __restrict__ img, float* __restrict__ out) {
    extern __shared__ uint4 slut[];
    for (int i = threadIdx.x; i < L3c; i += 512) slut[i] = g_lutp[i];
    __syncthreads();

    const float4* in4 = (const float4*)img;
    float4* out4 = (float4*)out;
    const int stride = gridDim.x * blockDim.x;

    for (int idx = blockIdx.x * blockDim.x + threadIdx.x; idx < TOTALG;
         idx += stride) {
        int bb = (idx >= Gc) ? 1 : 0;
        int p  = idx - bb * Gc;
        const float4* bi = in4 + (size_t)bb * 3 * Gc;
        float4 rr = bi[p];
        float4 gg = bi[p + Gc];
        float4 bz = bi[p + 2 * Gc];

        float4 q0, q1, q2;
        px_one(slut, rr.x, gg.x, bz.x, q0.x, q1.x, q2.x);
        px_one(slut, rr.y, gg.y, bz.y, q0.y, q1.y, q2.y);
        px_one(slut, rr.z, gg.z, bz.z, q0.z, q1.z, q2.z);
        px_one(slut, rr.w, gg.w, bz.w, q0.w, q1.w, q2.w);

        float4* bo = out4 + (size_t)bb * 3 * Gc;
        bo[p]          = q0;
        bo[p + Gc]     = q1;
        bo[p + 2 * Gc] = q2;
    }
}

extern "C" void kernel_launch(void* const* d_in, const int* in_sizes, int n_in,
                              void* d_out, int out_size) {
    const float* img = (const float*)d_in[0];
    const float* lut = (const float*)d_in[1];
    const float* ccm = (const float*)d_in[2];
    float* out = (float*)d_out;

    cudaFuncSetAttribute(lut_kernel,
                         cudaFuncAttributeMaxDynamicSharedMemorySize,
                         SMEM_BYTES);

    prep_kernel<<<(L3c + 255) / 256, 256>>>(lut, ccm);
    lut_kernel<<<296, 512, SMEM_BYTES>>>(img, out);
}

// round 3
// speedup vs baseline: 1.6574x; 1.5795x over previous
#include <cuda_runtime.h>
#include <cuda_fp16.h>
#include <cstdint>

namespace {
constexpr int L3c  = 17 * 17 * 17;     // 4913 LUT entries
constexpr int HWc  = 1080 * 1920;      // pixels per plane
constexpr int Gc   = HWc / 4;          // float4 groups per plane
constexpr int TOTALG = 2 * Gc;         // both batches
constexpr int SMEM_BYTES = L3c * 16;   // 78,608 B (one uint4 per entry)
constexpr int TPB = 640;               // 2 CTAs/SM -> 40 warps/SM (reg-capped 43)
}

// Pair-packed folded LUT: entry i holds fp16 {e0,e1,e2} of i and of i+1.
// e[i] = clip(rint(lut[i]*127),-127,127) @ ccm.T  (CCM folded into LUT).
__device__ uint4 g_lutp[L3c];

__device__ __forceinline__ void fold_entry(const float* __restrict__ lut,
                                           const float* __restrict__ ccm,
                                           int i, float& e0, float& e1, float& e2) {
    float w0 = fminf(fmaxf(rintf(lut[3 * i + 0] * 127.0f), -127.0f), 127.0f);
    float w1 = fminf(fmaxf(rintf(lut[3 * i + 1] * 127.0f), -127.0f), 127.0f);
    float w2 = fminf(fmaxf(rintf(lut[3 * i + 2] * 127.0f), -127.0f), 127.0f);
    e0 = w0 * ccm[0] + w1 * ccm[1] + w2 * ccm[2];
    e1 = w0 * ccm[3] + w1 * ccm[4] + w2 * ccm[5];
    e2 = w0 * ccm[6] + w1 * ccm[7] + w2 * ccm[8];
}

__global__ void prep_kernel(const float* __restrict__ lut,
                            const float* __restrict__ ccm) {
    int i = blockIdx.x * blockDim.x + threadIdx.x;
    if (i >= L3c) return;
    float a0, a1, a2, b0, b1, b2;
    fold_entry(lut, ccm, i, a0, a1, a2);
    int j = (i + 1 < L3c) ? i + 1 : i;   // guard; last entry's pair never read
    fold_entry(lut, ccm, j, b0, b1, b2);
    __half2 h01 = __floats2half2_rn(a0, a1);
    __half2 h23 = __floats2half2_rn(a2, b0);
    __half2 h45 = __floats2half2_rn(b1, b2);
    uint4 v;
    v.x = *reinterpret_cast<uint32_t*>(&h01);
    v.y = *reinterpret_cast<uint32_t*>(&h23);
    v.z = *reinterpret_cast<uint32_t*>(&h45);
    v.w = 0u;
    g_lutp[i] = v;
}

__device__ __forceinline__ float lerpf(float a, float b, float t) {
    return fmaf(b - a, t, a);
}

// Decode one pair entry and lerp along b in one go.
__device__ __forceinline__ void pair_blerp(uint4 P, float fb,
                                           float& q0, float& q1, float& q2) {
    float2 a = __half22float2(*reinterpret_cast<__half2*>(&P.x)); // e0(b1), e1(b1)
    float2 b = __half22float2(*reinterpret_cast<__half2*>(&P.y)); // e2(b1), e0(b2)
    float2 c = __half22float2(*reinterpret_cast<__half2*>(&P.z)); // e1(b2), e2(b2)
    q0 = lerpf(a.x, b.y, fb);
    q1 = lerpf(a.y, c.x, fb);
    q2 = lerpf(b.x, c.y, fb);
}

__device__ __forceinline__ void px_one(const uint4* __restrict__ slut,
                                       float r, float g, float b,
                                       float& o0, float& o1, float& o2) {
    float rf = r * 0.0625f, gf = g * 0.0625f, bf = b * 0.0625f;
    float rfl = floorf(rf), gfl = floorf(gf), bfl = floorf(bf);
    float fr = rf - rfl, fg = gf - gfl, fb = bf - bfl;
    // base = r1*289 + g1*17 + b1 (exact in fp32; max 4605). img<256 -> no clip.
    int base = (int)fmaf(rfl, 289.0f, fmaf(gfl, 17.0f, bfl));
    const uint4* c = slut + base;
    uint4 P00 = c[0];     // (r1,g1) b-pair
    uint4 P01 = c[17];    // (r1,g2)
    uint4 P10 = c[289];   // (r2,g1)
    uint4 P11 = c[306];   // (r2,g2)

    float a0, a1, a2, b0, b1, b2, d0, d1, d2, e0, e1, e2;
    pair_blerp(P00, fb, a0, a1, a2);
    pair_blerp(P01, fb, b0, b1, b2);
    pair_blerp(P10, fb, d0, d1, d2);
    pair_blerp(P11, fb, e0, e1, e2);

    float c0x = lerpf(a0, b0, fg);
    float c0y = lerpf(a1, b1, fg);
    float c0z = lerpf(a2, b2, fg);
    float c1x = lerpf(d0, e0, fg);
    float c1y = lerpf(d1, e1, fg);
    float c1z = lerpf(d2, e2, fg);

    o0 = fminf(fmaxf(lerpf(c0x, c1x, fr), 1e-8f), 1.0f);
    o1 = fminf(fmaxf(lerpf(c0y, c1y, fr), 1e-8f), 1.0f);
    o2 = fminf(fmaxf(lerpf(c0z, c1z, fr), 1e-8f), 1.0f);
}

__global__ void __launch_bounds__(TPB, 2)
lut_kernel(const float* __restrict__ img, float* __restrict__ out) {
    extern __shared__ uint4 slut[];
    for (int i = threadIdx.x; i < L3c; i += TPB) slut[i] = g_lutp[i];
    __syncthreads();

    const float4* in4 = (const float4*)img;
    float4* out4 = (float4*)out;
    const int stride = gridDim.x * blockDim.x;

    for (int idx = blockIdx.x * blockDim.x + threadIdx.x; idx < TOTALG;
         idx += stride) {
        int bb = (idx >= Gc) ? 1 : 0;
        int p  = idx - bb * Gc;
        const float4* bi = in4 + (size_t)bb * 3 * Gc;
        float4 rr = bi[p];
        float4 gg = bi[p + Gc];
        float4 bz = bi[p + 2 * Gc];

        float4 q0, q1, q2;
        px_one(slut, rr.x, gg.x, bz.x, q0.x, q1.x, q2.x);
        px_one(slut, rr.y, gg.y, bz.y, q0.y, q1.y, q2.y);
        px_one(slut, rr.z, gg.z, bz.z, q0.z, q1.z, q2.z);
        px_one(slut, rr.w, gg.w, bz.w, q0.w, q1.w, q2.w);

        float4* bo = out4 + (size_t)bb * 3 * Gc;
        bo[p]          = q0;
        bo[p + Gc]     = q1;
        bo[p + 2 * Gc] = q2;
    }
}

extern "C" void kernel_launch(void* const* d_in, const int* in_sizes, int n_in,
                              void* d_out, int out_size) {
    const float* img = (const float*)d_in[0];
    const float* lut = (const float*)d_in[1];
    const float* ccm = (const float*)d_in[2];
    float* out = (float*)d_out;

    cudaFuncSetAttribute(lut_kernel,
                         cudaFuncAttributeMaxDynamicSharedMemorySize,
                         SMEM_BYTES);

    prep_kernel<<<(L3c + 255) / 256, 256>>>(lut, ccm);
    lut_kernel<<<296, TPB, SMEM_BYTES>>>(img, out);
}

// round 4
// speedup vs baseline: 1.9124x; 1.1538x over previous
#include <cuda_runtime.h>
#include <cstdint>

namespace {
constexpr int L3c  = 17 * 17 * 17;     // 4913 LUT entries
constexpr int HWc  = 1080 * 1920;      // pixels per plane
constexpr int Gc   = HWc / 4;          // float4 groups per plane
constexpr int TOTALG = 2 * Gc;         // both batches
constexpr int SMEM_BYTES = L3c * 16;   // 78,608 B (one uint4 face-entry)
constexpr int TPB = 640;               // 2 CTAs/SM -> 40 warps/SM
}

// Face-packed LUT: entry (r,g,b) holds biased-uint8 weights u = w+128 for the
// 4 nodes of the (g,b) face at plane r: n00=(g,b), n01=(g,b+1), n10=(g+1,b),
// n11=(g+1,b+1), 3 channels each = 12 bytes in a uint4.
__device__ uint4 g_face[L3c];
// Prescaled CCM (ccm[c][k]/256) and bias_c = -(K/256)*sum_k ccm[c][k],
// where decoded raw value V = K + 256*w, K = 2^23 + 32768.
__device__ float g_cs[9];
__device__ float g_bias[3];

__device__ __forceinline__ uint32_t qw(const float* __restrict__ lut, int n, int c) {
    float w = fminf(fmaxf(rintf(lut[3 * n + c] * 127.0f), -127.0f), 127.0f);
    return (uint32_t)(int)(w + 128.0f);   // biased to [1,255]
}

__global__ void prep_kernel(const float* __restrict__ lut,
                            const float* __restrict__ ccm) {
    int i = blockIdx.x * blockDim.x + threadIdx.x;
    if (i >= L3c) return;
    int n00 = i;
    int n01 = (i + 1  < L3c) ? i + 1  : L3c - 1;   // clamp; unused entries only
    int n10 = (i + 17 < L3c) ? i + 17 : L3c - 1;
    int n11 = (i + 18 < L3c) ? i + 18 : L3c - 1;
    uint4 v;
    v.x = qw(lut,n00,0) | (qw(lut,n00,1) << 8) | (qw(lut,n00,2) << 16) | (qw(lut,n01,0) << 24);
    v.y = qw(lut,n01,1) | (qw(lut,n01,2) << 8) | (qw(lut,n10,0) << 16) | (qw(lut,n10,1) << 24);
    v.z = qw(lut,n10,2) | (qw(lut,n11,0) << 8) | (qw(lut,n11,1) << 16) | (qw(lut,n11,2) << 24);
    v.w = 0u;
    g_face[i] = v;
    if (i < 3) {
        const float K = 8421376.0f;  // 2^23 + 32768
        float s = 0.0f;
        for (int k = 0; k < 3; k++) {
            g_cs[i * 3 + k] = ccm[i * 3 + k] * (1.0f / 256.0f);
            s += ccm[i * 3 + k];
        }
        g_bias[i] = -(K / 256.0f) * s;
    }
}

// Decode byte k of word: float with value 2^23 + 256*u  (exact).
__device__ __forceinline__ float dec(uint32_t word, int k) {
    return __uint_as_float(__byte_perm(word, 0x4B000000u, 0x7504u | (k << 4)));
}

// Bilinear over one packed face -> 3 raw channel values.
__device__ __forceinline__ void face_bilerp(uint4 F, float fb, float ifb,
                                            float fg, float ifg,
                                            float& r0, float& r1, float& r2) {
    float n00c0 = dec(F.x, 0), n00c1 = dec(F.x, 1), n00c2 = dec(F.x, 2);
    float n01c0 = dec(F.x, 3), n01c1 = dec(F.y, 0), n01c2 = dec(F.y, 1);
    float n10c0 = dec(F.y, 2), n10c1 = dec(F.y, 3), n10c2 = dec(F.z, 0);
    float n11c0 = dec(F.z, 1), n11c1 = dec(F.z, 2), n11c2 = dec(F.z, 3);
    float t0, t1;
    t0 = fmaf(n01c0, fb, n00c0 * ifb);
    t1 = fmaf(n11c0, fb, n10c0 * ifb);
    r0 = fmaf(t1, fg, t0 * ifg);
    t0 = fmaf(n01c1, fb, n00c1 * ifb);
    t1 = fmaf(n11c1, fb, n10c1 * ifb);
    r1 = fmaf(t1, fg, t0 * ifg);
    t0 = fmaf(n01c2, fb, n00c2 * ifb);
    t1 = fmaf(n11c2, fb, n10c2 * ifb);
    r2 = fmaf(t1, fg, t0 * ifg);
}

__device__ __forceinline__ void px_one(const uint4* __restrict__ slut,
                                       const float* cs, const float* bias,
                                       float r, float g, float b,
                                       float& o0, float& o1, float& o2) {
    float rf = r * 0.0625f, gf = g * 0.0625f, bf = b * 0.0625f;
    float rfl = floorf(rf), gfl = floorf(gf), bfl = floorf(bf);
    float fr = rf - rfl, fg = gf - gfl, fb = bf - bfl;
    float ifr = 1.0f - fr, ifg = 1.0f - fg, ifb = 1.0f - fb;
    // base = r1*289 + g1*17 + b1 (exact fp32 FMA; max 4605). img<256 -> no clip.
    int base = (int)fmaf(rfl, 289.0f, fmaf(gfl, 17.0f, bfl));
    uint4 FA = slut[base];          // r1 face
    uint4 FB = slut[base + 289];    // r2 face

    float a0, a1, a2, b0, b1, b2;
    face_bilerp(FA, fb, ifb, fg, ifg, a0, a1, a2);
    face_bilerp(FB, fb, ifb, fg, ifg, b0, b1, b2);

    float R0 = fmaf(b0, fr, a0 * ifr);   // raw = K + 256*w_interp
    float R1 = fmaf(b1, fr, a1 * ifr);
    float R2 = fmaf(b2, fr, a2 * ifr);

    float u0 = fmaf(cs[0], R0, fmaf(cs[1], R1, fmaf(cs[2], R2, bias[0])));
    float u1 = fmaf(cs[3], R0, fmaf(cs[4], R1, fmaf(cs[5], R2, bias[1])));
    float u2 = fmaf(cs[6], R0, fmaf(cs[7], R1, fmaf(cs[8], R2, bias[2])));

    o0 = fminf(fmaxf(u0, 1e-8f), 1.0f);
    o1 = fminf(fmaxf(u1, 1e-8f), 1.0f);
    o2 = fminf(fmaxf(u2, 1e-8f), 1.0f);
}

__global__ void __launch_bounds__(TPB, 2)
lut_kernel(const float* __restrict__ img, float* __restrict__ out) {
    extern __shared__ uint4 slut[];
    for (int i = threadIdx.x; i < L3c; i += TPB) slut[i] = g_face[i];
    __syncthreads();

    float cs[9], bias[3];
#pragma unroll
    for (int k = 0; k < 9; k++) cs[k] = g_cs[k];
#pragma unroll
    for (int k = 0; k < 3; k++) bias[k] = g_bias[k];

    const float4* in4 = (const float4*)img;
    float4* out4 = (float4*)out;
    const int stride = gridDim.x * blockDim.x;

    for (int idx = blockIdx.x * blockDim.x + threadIdx.x; idx < TOTALG;
         idx += stride) {
        int bb = (idx >= Gc) ? 1 : 0;
        int p  = idx - bb * Gc;
        const float4* bi = in4 + (size_t)bb * 3 * Gc;
        float4 rr = bi[p];
        float4 gg = bi[p + Gc];
        float4 bz = bi[p + 2 * Gc];

        float4 q0, q1, q2;
        px_one(slut, cs, bias, rr.x, gg.x, bz.x, q0.x, q1.x, q2.x);
        px_one(slut, cs, bias, rr.y, gg.y, bz.y, q0.y, q1.y, q2.y);
        px_one(slut, cs, bias, rr.z, gg.z, bz.z, q0.z, q1.z, q2.z);
        px_one(slut, cs, bias, rr.w, gg.w, bz.w, q0.w, q1.w, q2.w);

        float4* bo = out4 + (size_t)bb * 3 * Gc;
        bo[p]          = q0;
        bo[p + Gc]     = q1;
        bo[p + 2 * Gc] = q2;
    }
}

extern "C" void kernel_launch(void* const* d_in, const int* in_sizes, int n_in,
                              void* d_out, int out_size) {
    const float* img = (const float*)d_in[0];
    const float* lut = (const float*)d_in[1];
    const float* ccm = (const float*)d_in[2];
    float* out = (float*)d_out;

    cudaFuncSetAttribute(lut_kernel,
                         cudaFuncAttributeMaxDynamicSharedMemorySize,
                         SMEM_BYTES);

    prep_kernel<<<(L3c + 255) / 256, 256>>>(lut, ccm);
    lut_kernel<<<296, TPB, SMEM_BYTES>>>(img, out);
}